// round 10
// baseline (speedup 1.0000x reference)
#include <cuda_runtime.h>
#include <cuda_bf16.h>

// WTA / row-wise top-k(=64) scatter-to-dense, exact incl. stable tie-breaking.
// 1 CTA per row (TPB=512), row as raw floats in registers (4x float4).
// Key structure: the output row is zero-filled IMMEDIATELY at CTA start
// (independent of the data -> overlaps the load/hist/select critical path),
// and after threshold selection only the ~k winners are scatter-written.
// Each thread's scatter targets are inside its own zeroed float4 slots, so
// same-thread program order makes the zero->winner overwrite safe, no fence.
// Fast path (valid when count(f>=1.5) >= k, always true for N(0,1) rows):
//   (1) fused 256-bin histogram of (bits>>16)-0x3FC0 over f >= 1.5 with
//       per-bin slot capture of full bits ([1.5,6) spans exactly 256 bins)
//   (2) warp0: pick bin where reverse-cumulative crosses k, shuffle-rank the
//       <=16 captured elements -> exact k-th value + tie metadata
//   (3) scatter winners: f >= thr (rare stable tie-break by column order).
// Generic fallback (cold, exact): 4-pass 256-bin radix select over fmap keys.

#define COLS  8192
#define TPB   512
#define VPT   4                    // float4 per thread -> 16 scalars
#define NW    (TPB / 32)
#define SLOTS 16
#define FULL  0xffffffffu

__device__ __forceinline__ unsigned fmap_u(unsigned b) {
    return b ^ ((unsigned)((int)b >> 31) | 0x80000000u);
}
__device__ __forceinline__ float funmap(unsigned v) {
    unsigned mask = ((unsigned)((int)(~v) >> 31)) | 0x80000000u;
    return __uint_as_float(v ^ mask);
}

__global__ __launch_bounds__(TPB, 4)
void wta_topk_kernel(const float4* __restrict__ x4,
                     const int*    __restrict__ kp,
                     float4*       __restrict__ o4)
{
    __shared__ unsigned sHist[256];
    __shared__ unsigned sBin[256 * SLOTS];
    __shared__ unsigned sWsum[NW];
    __shared__ unsigned sSel, sNeed, sEq, sThr, sFlag;

    const int tid  = threadIdx.x;
    const int lane = tid & 31;
    const int warp = tid >> 5;
    const size_t base = (size_t)blockIdx.x * (COLS / 4) + tid;
    float* const out = (float*)o4;

    // ---- issue row loads ----
    float4 v[VPT];
#pragma unroll
    for (int j = 0; j < VPT; j++)
        v[j] = __ldcs(&x4[base + (size_t)j * TPB]);
    const unsigned k = (unsigned)__ldg(kp);

    // ---- zero-fill output row NOW (independent of loads; overlaps them and
    //      the whole hist/select phase; winners overwritten by same thread) ----
    const float4 z = make_float4(0.0f, 0.0f, 0.0f, 0.0f);
#pragma unroll
    for (int j = 0; j < VPT; j++)
        o4[base + (size_t)j * TPB] = z;

    if (tid < 256) sHist[tid] = 0u;
    if (tid == 0) sFlag = 0u;
    __syncthreads();                                              // S1

    // ---- (1) fused histogram + per-bin slot capture over f >= 1.5 ----
#pragma unroll
    for (int j = 0; j < VPT; j++) {
#pragma unroll
        for (int c = 0; c < 4; c++) {
            const float f = (c == 0) ? v[j].x : (c == 1) ? v[j].y
                          : (c == 2) ? v[j].z : v[j].w;
            if (f >= 1.5f) {
                const unsigned bits = __float_as_uint(f);
                unsigned b = (bits >> 16) - 0x3FC0u;
                b = min(b, 255u);
                const unsigned p = atomicAdd(&sHist[b], 1u);
                if (p < SLOTS) sBin[(b << 4) + p] = bits;
            }
        }
    }
    __syncthreads();                                              // S2

    // ---- (2) warp0: bin select + in-bin shuffle rank ----
    if (warp == 0) {
        unsigned hv8[8], tot[8];
#pragma unroll
        for (int c = 0; c < 8; c++) {
            hv8[c] = sHist[c * 32 + lane];
            tot[c] = __reduce_add_sync(FULL, hv8[c]);
        }
        unsigned suf = 0u, tch = 0u, exC = 0u;
#pragma unroll
        for (int c = 7; c >= 0; c--) {
            if (suf < k && k <= suf + tot[c]) { tch = (unsigned)c; exC = suf; }
            suf += tot[c];
        }
        if (suf < k) {
            if (lane == 0) sFlag = 1u;
        } else {
            const unsigned hv = hv8[tch];
            unsigned incl = hv;            // suffix sum over higher bins
#pragma unroll
            for (int o = 1; o < 32; o <<= 1) {
                const unsigned n = __shfl_down_sync(FULL, incl, o);
                if (lane + o < 32) incl += n;
            }
            const unsigned excl = incl - hv;
            const bool fired = (exC + excl < k) && (k <= exC + incl);
            const unsigned fm = __ballot_sync(FULL, fired);
            const int src = __ffs(fm) - 1;
            const unsigned selBin = tch * 32u + (unsigned)src;
            const unsigned need1  = k - exC - __shfl_sync(FULL, excl, src);
            const unsigned E      = __shfl_sync(FULL, hv, src);
            if (E > SLOTS) {
                if (lane == 0) sFlag = 1u;
            } else {
                // exact rank among E (<=16) captured keys; positive-float
                // bits compare identically to values.
                const unsigned key = (lane < (int)E)
                                   ? sBin[(selBin << 4) + lane] : 0u;
                unsigned gt = 0u, eq = 0u;
#pragma unroll
                for (int o = 0; o < SLOTS; o++) {
                    const unsigned other = __shfl_sync(FULL, key, o);
                    if (o < (int)E) {
                        gt += (other > key) ? 1u : 0u;
                        eq += (other == key) ? 1u : 0u;
                    }
                }
                if (gt < need1 && need1 <= gt + eq) {   // unique key fires
                    sThr  = key;
                    sNeed = need1 - gt;
                    sEq   = eq;
                }
            }
        }
    }
    __syncthreads();                                              // S3

    float thrF;
    unsigned need, eqCnt;
    if (sFlag == 0u) {
        thrF  = __uint_as_float(sThr);
        need  = sNeed;
        eqCnt = sEq;
    } else {
        // ---- generic fallback: 4-pass 256-bin radix over fmap keys ----
        unsigned prefix = 0u;
        need = k;
#pragma unroll 1
        for (int p = 3; p >= 0; p--) {
            const int sh = 8 * p;
            __syncthreads();
            if (tid < 256) sHist[tid] = 0u;
            __syncthreads();
#pragma unroll 1
            for (int j = 0; j < VPT; j++) {
                const float e[4] = { v[j].x, v[j].y, v[j].z, v[j].w };
#pragma unroll
                for (int c = 0; c < 4; c++) {
                    const unsigned key = fmap_u(__float_as_uint(e[c]));
                    const bool m = (p == 3) || (((key ^ prefix) >> (sh + 8)) == 0u);
                    if (m) atomicAdd(&sHist[(key >> sh) & 255u], 1u);
                }
            }
            __syncthreads();
            if (warp == 0) {
                unsigned hv8[8], tot[8];
#pragma unroll
                for (int c = 0; c < 8; c++) {
                    hv8[c] = sHist[c * 32 + lane];
                    tot[c] = __reduce_add_sync(FULL, hv8[c]);
                }
                unsigned suf = 0u, tch = 0u, exC = 0u;
#pragma unroll
                for (int c = 7; c >= 0; c--) {
                    if (suf < need && need <= suf + tot[c]) { tch = (unsigned)c; exC = suf; }
                    suf += tot[c];
                }
                const unsigned hv = hv8[tch];
                unsigned incl = hv;
#pragma unroll
                for (int o = 1; o < 32; o <<= 1) {
                    const unsigned n = __shfl_down_sync(FULL, incl, o);
                    if (lane + o < 32) incl += n;
                }
                const unsigned excl = incl - hv;
                if (exC + excl < need && need <= exC + incl) {
                    sSel  = tch * 32 + (unsigned)lane;
                    sNeed = need - exC - excl;
                    sEq   = hv;
                }
            }
            __syncthreads();
            prefix |= sSel << sh;
            need   = sNeed;
        }
        eqCnt = sEq;
        thrF  = funmap(prefix);
    }

    // ---- (3) scatter winners over the pre-zeroed row ----
    if (need == eqCnt) {
        // common path: write all f >= thrF (~k sparse stores CTA-wide)
#pragma unroll
        for (int j = 0; j < VPT; j++) {
            const size_t a = (base + (size_t)j * TPB) * 4;
            if (v[j].x >= thrF) out[a + 0] = v[j].x;
            if (v[j].y >= thrF) out[a + 1] = v[j].y;
            if (v[j].z >= thrF) out[a + 2] = v[j].z;
            if (v[j].w >= thrF) out[a + 3] = v[j].w;
        }
    } else {
        // rare: stable tie-break, keep first `need` of ==thrF by column order
        unsigned keepMask = 0u, running = 0u;
#pragma unroll 1
        for (int j = 0; j < VPT; j++) {
            const float e[4] = { v[j].x, v[j].y, v[j].z, v[j].w };
            unsigned eq[4], lc = 0u;
#pragma unroll
            for (int c = 0; c < 4; c++) {
                eq[c] = (e[c] == thrF) ? 1u : 0u;
                lc += eq[c];
            }
            unsigned pre = lc;
#pragma unroll
            for (int o = 1; o < 32; o <<= 1) {
                const unsigned n = __shfl_up_sync(FULL, pre, o);
                if (lane >= o) pre += n;
            }
            const unsigned excl = pre - lc;
            __syncthreads();
            if (lane == 31) sWsum[warp] = pre;
            __syncthreads();
            unsigned off = 0u, tot = 0u;
#pragma unroll
            for (int w = 0; w < NW; w++) {
                const unsigned t = sWsum[w];
                if (w < warp) off += t;
                tot += t;
            }
            unsigned r = running + off + excl;
#pragma unroll
            for (int c = 0; c < 4; c++) {
                if (eq[c]) {
                    if (r < need) keepMask |= 1u << (4 * j + c);
                    r++;
                }
            }
            running += tot;
        }
#pragma unroll
        for (int j = 0; j < VPT; j++) {
            const float e[4] = { v[j].x, v[j].y, v[j].z, v[j].w };
            const size_t a = (base + (size_t)j * TPB) * 4;
#pragma unroll
            for (int c = 0; c < 4; c++) {
                const int i = 4 * j + c;
                const bool keep = (e[c] > thrF) ||
                                  ((e[c] == thrF) && ((keepMask >> i) & 1u));
                if (keep) out[a + c] = e[c];
            }
        }
    }
}

extern "C" void kernel_launch(void* const* d_in, const int* in_sizes, int n_in,
                              void* d_out, int out_size) {
    const float4* x4 = (const float4*)d_in[0];
    const int*    kp = (const int*)d_in[1];
    float4*       o4 = (float4*)d_out;
    const int rows = in_sizes[0] / COLS;
    wta_topk_kernel<<<rows, TPB>>>(x4, kp, o4);
}

// round 11
// speedup vs baseline: 1.1106x; 1.1106x over previous
#include <cuda_runtime.h>
#include <cuda_bf16.h>

// WTA / row-wise top-k(=64) scatter-to-dense, exact incl. stable tie-breaking.
// 1 CTA per row (TPB=512), row as raw floats in registers (4x float4).
// Fast path (valid when count(f>=1.5) >= k, always true for N(0,1) rows):
//   (1) fused 256-bin histogram of (bits>>16)-0x3FC0 over f >= 1.5 with
//       per-bin slot capture of full bits ([1.5,6) spans exactly 256 bins)
//   (2) warp0: pick bin where reverse-cumulative crosses k, then rank the
//       E (expected 2-4, dynamically bounded) captured elements with a
//       shuffle loop -> exact k-th value + tie metadata
//   (3) output: out = (f >= thr) ? f : 0 ; rare stable tie-break by column.
// Generic fallback (cold, exact): 4-pass 256-bin radix select over fmap keys.

#define COLS  8192
#define TPB   512
#define VPT   4                    // float4 per thread -> 16 scalars
#define NW    (TPB / 32)
#define SLOTS 16
#define FULL  0xffffffffu

__device__ __forceinline__ unsigned fmap_u(unsigned b) {
    return b ^ ((unsigned)((int)b >> 31) | 0x80000000u);
}
__device__ __forceinline__ float funmap(unsigned v) {
    unsigned mask = ((unsigned)((int)(~v) >> 31)) | 0x80000000u;
    return __uint_as_float(v ^ mask);
}

__global__ __launch_bounds__(TPB, 4)
void wta_topk_kernel(const float4* __restrict__ x4,
                     const int*    __restrict__ kp,
                     float4*       __restrict__ o4)
{
    __shared__ unsigned sHist[256];
    __shared__ unsigned sBin[256 * SLOTS];
    __shared__ unsigned sWsum[NW];
    __shared__ unsigned sSel, sNeed, sEq, sThr, sFlag;

    const int tid  = threadIdx.x;
    const int lane = tid & 31;
    const int warp = tid >> 5;
    const size_t base = (size_t)blockIdx.x * (COLS / 4) + tid;

    // ---- load row (raw floats) ----
    float4 v[VPT];
#pragma unroll
    for (int j = 0; j < VPT; j++)
        v[j] = __ldcs(&x4[base + (size_t)j * TPB]);
    const unsigned k = (unsigned)__ldg(kp);

    if (tid < 256) sHist[tid] = 0u;
    if (tid == 0) sFlag = 0u;
    __syncthreads();                                              // S1

    // ---- (1) fused histogram + per-bin slot capture over f >= 1.5 ----
#pragma unroll
    for (int j = 0; j < VPT; j++) {
#pragma unroll
        for (int c = 0; c < 4; c++) {
            const float f = (c == 0) ? v[j].x : (c == 1) ? v[j].y
                          : (c == 2) ? v[j].z : v[j].w;
            if (f >= 1.5f) {
                const unsigned bits = __float_as_uint(f);
                unsigned b = (bits >> 16) - 0x3FC0u;
                b = min(b, 255u);
                const unsigned p = atomicAdd(&sHist[b], 1u);
                if (p < SLOTS) sBin[(b << 4) + p] = bits;
            }
        }
    }
    __syncthreads();                                              // S2

    // ---- (2) warp0: bin select + dynamic-length in-bin shuffle rank ----
    if (warp == 0) {
        unsigned hv8[8], tot[8];
#pragma unroll
        for (int c = 0; c < 8; c++) {
            hv8[c] = sHist[c * 32 + lane];
            tot[c] = __reduce_add_sync(FULL, hv8[c]);
        }
        unsigned suf = 0u, tch = 0u, exC = 0u;
#pragma unroll
        for (int c = 7; c >= 0; c--) {
            if (suf < k && k <= suf + tot[c]) { tch = (unsigned)c; exC = suf; }
            suf += tot[c];
        }
        if (suf < k) {
            if (lane == 0) sFlag = 1u;
        } else {
            const unsigned hv = hv8[tch];
            unsigned incl = hv;            // suffix sum over higher bins
#pragma unroll
            for (int o = 1; o < 32; o <<= 1) {
                const unsigned n = __shfl_down_sync(FULL, incl, o);
                if (lane + o < 32) incl += n;
            }
            const unsigned excl = incl - hv;
            const bool fired = (exC + excl < k) && (k <= exC + incl);
            const unsigned fm = __ballot_sync(FULL, fired);
            const int src = __ffs(fm) - 1;
            const unsigned selBin = tch * 32u + (unsigned)src;
            const unsigned need1  = k - exC - __shfl_sync(FULL, excl, src);
            const unsigned E      = __shfl_sync(FULL, hv, src);
            if (E > SLOTS) {
                if (lane == 0) sFlag = 1u;
            } else {
                // exact rank among E captured keys, loop bounded by E
                // (warp-uniform, expected 2-4). Positive-float bits compare
                // identically to values.
                const unsigned key = (lane < (int)E)
                                   ? sBin[(selBin << 4) + lane] : 0u;
                unsigned gt = 0u, eq = 0u;
                for (int o = 0; o < (int)E; o++) {
                    const unsigned other = __shfl_sync(FULL, key, o);
                    gt += (other > key) ? 1u : 0u;
                    eq += (other == key) ? 1u : 0u;
                }
                if (lane < (int)E && gt < need1 && need1 <= gt + eq) {
                    sThr  = key;            // unique key value fires
                    sNeed = need1 - gt;
                    sEq   = eq;
                }
            }
        }
    }
    __syncthreads();                                              // S3

    float thrF;
    unsigned need, eqCnt;
    if (sFlag == 0u) {
        thrF  = __uint_as_float(sThr);
        need  = sNeed;
        eqCnt = sEq;
    } else {
        // ---- generic fallback: 4-pass 256-bin radix over fmap keys ----
        unsigned prefix = 0u;
        need = k;
#pragma unroll 1
        for (int p = 3; p >= 0; p--) {
            const int sh = 8 * p;
            __syncthreads();
            if (tid < 256) sHist[tid] = 0u;
            __syncthreads();
#pragma unroll 1
            for (int j = 0; j < VPT; j++) {
                const float e[4] = { v[j].x, v[j].y, v[j].z, v[j].w };
#pragma unroll
                for (int c = 0; c < 4; c++) {
                    const unsigned key = fmap_u(__float_as_uint(e[c]));
                    const bool m = (p == 3) || (((key ^ prefix) >> (sh + 8)) == 0u);
                    if (m) atomicAdd(&sHist[(key >> sh) & 255u], 1u);
                }
            }
            __syncthreads();
            if (warp == 0) {
                unsigned hv8[8], tot[8];
#pragma unroll
                for (int c = 0; c < 8; c++) {
                    hv8[c] = sHist[c * 32 + lane];
                    tot[c] = __reduce_add_sync(FULL, hv8[c]);
                }
                unsigned suf = 0u, tch = 0u, exC = 0u;
#pragma unroll
                for (int c = 7; c >= 0; c--) {
                    if (suf < need && need <= suf + tot[c]) { tch = (unsigned)c; exC = suf; }
                    suf += tot[c];
                }
                const unsigned hv = hv8[tch];
                unsigned incl = hv;
#pragma unroll
                for (int o = 1; o < 32; o <<= 1) {
                    const unsigned n = __shfl_down_sync(FULL, incl, o);
                    if (lane + o < 32) incl += n;
                }
                const unsigned excl = incl - hv;
                if (exC + excl < need && need <= exC + incl) {
                    sSel  = tch * 32 + (unsigned)lane;
                    sNeed = need - exC - excl;
                    sEq   = hv;
                }
            }
            __syncthreads();
            prefix |= sSel << sh;
            need   = sNeed;
        }
        eqCnt = sEq;
        thrF  = funmap(prefix);
    }

    // ---- (3) output ----
    if (need == eqCnt) {
        // common path: keep all f >= thrF
#pragma unroll
        for (int j = 0; j < VPT; j++) {
            float4 o;
            o.x = (v[j].x >= thrF) ? v[j].x : 0.0f;
            o.y = (v[j].y >= thrF) ? v[j].y : 0.0f;
            o.z = (v[j].z >= thrF) ? v[j].z : 0.0f;
            o.w = (v[j].w >= thrF) ? v[j].w : 0.0f;
            __stcs(&o4[base + (size_t)j * TPB], o);
        }
    } else {
        // rare: stable tie-break, keep first `need` of ==thrF by column order
        unsigned keepMask = 0u, running = 0u;
#pragma unroll 1
        for (int j = 0; j < VPT; j++) {
            const float e[4] = { v[j].x, v[j].y, v[j].z, v[j].w };
            unsigned eq[4], lc = 0u;
#pragma unroll
            for (int c = 0; c < 4; c++) {
                eq[c] = (e[c] == thrF) ? 1u : 0u;
                lc += eq[c];
            }
            unsigned pre = lc;
#pragma unroll
            for (int o = 1; o < 32; o <<= 1) {
                const unsigned n = __shfl_up_sync(FULL, pre, o);
                if (lane >= o) pre += n;
            }
            const unsigned excl = pre - lc;
            __syncthreads();
            if (lane == 31) sWsum[warp] = pre;
            __syncthreads();
            unsigned off = 0u, tot = 0u;
#pragma unroll
            for (int w = 0; w < NW; w++) {
                const unsigned t = sWsum[w];
                if (w < warp) off += t;
                tot += t;
            }
            unsigned r = running + off + excl;
#pragma unroll
            for (int c = 0; c < 4; c++) {
                if (eq[c]) {
                    if (r < need) keepMask |= 1u << (4 * j + c);
                    r++;
                }
            }
            running += tot;
        }
#pragma unroll
        for (int j = 0; j < VPT; j++) {
            const float e[4] = { v[j].x, v[j].y, v[j].z, v[j].w };
            float o[4];
#pragma unroll
            for (int c = 0; c < 4; c++) {
                const int i = 4 * j + c;
                const bool keep = (e[c] > thrF) ||
                                  ((e[c] == thrF) && ((keepMask >> i) & 1u));
                o[c] = keep ? e[c] : 0.0f;
            }
            float4 ov = { o[0], o[1], o[2], o[3] };
            __stcs(&o4[base + (size_t)j * TPB], ov);
        }
    }
}

extern "C" void kernel_launch(void* const* d_in, const int* in_sizes, int n_in,
                              void* d_out, int out_size) {
    const float4* x4 = (const float4*)d_in[0];
    const int*    kp = (const int*)d_in[1];
    float4*       o4 = (float4*)d_out;
    const int rows = in_sizes[0] / COLS;
    wta_topk_kernel<<<rows, TPB>>>(x4, kp, o4);
}